// round 14
// baseline (speedup 1.0000x reference)
#include <cuda_runtime.h>
#include <cuda_bf16.h>
#include <cstdint>

// RBF kernel matrix, bf16-hi HMMA filter + rare precise recompute.
//   Bound: |sq_hi - sq| <= 0.008*(||x||^2+||y||^2)  (bf16 rn eps=2^-8, AM-GM, margin)
//   sq_hi >= 89.2 + 0.008*(x2+y2)  =>  sq > 88  =>  expf(-sq) underflows => 0.0f
//   else: exact fp32 recompute (rare).
// R14 delta vs R12: 512-thread CTA, 4x4 warp grid, 32x32 warp tile, 64 regs
// -> 32 warps/SM (2x occupancy). Same smem layout, filter, .cs stores, swizzle.
// x,y: [8192,128] f32. out: [8192,8192] f32.

#define NM 8192
#define KD 128
#define CTA_M 128
#define CTA_N 128
#define GRID_W (NM / CTA_N)
#define SUPER 8

__device__ float g_x2[NM];
__device__ float g_y2[NM];
__device__ __nv_bfloat16 g_xhi[NM * KD];
__device__ __nv_bfloat16 g_yhi[NM * KD];

// ---------------- helpers ----------------
__device__ __forceinline__ uint32_t smem_u32(const void* p) {
    uint32_t a;
    asm("{ .reg .u64 t; cvta.to.shared.u64 t, %1; cvt.u32.u64 %0, t; }"
        : "=r"(a) : "l"(p));
    return a;
}
__device__ __forceinline__ void ldsm_x4(uint32_t* r, uint32_t addr) {
    asm volatile("ldmatrix.sync.aligned.m8n8.x4.shared.b16 {%0,%1,%2,%3}, [%4];"
                 : "=r"(r[0]), "=r"(r[1]), "=r"(r[2]), "=r"(r[3]) : "r"(addr));
}
__device__ __forceinline__ void mma_bf16(float* d, const uint32_t* a, const uint32_t* b) {
    asm volatile(
        "mma.sync.aligned.m16n8k16.row.col.f32.bf16.bf16.f32 "
        "{%0,%1,%2,%3}, {%4,%5,%6,%7}, {%8,%9}, {%0,%1,%2,%3};"
        : "+f"(d[0]), "+f"(d[1]), "+f"(d[2]), "+f"(d[3])
        : "r"(a[0]), "r"(a[1]), "r"(a[2]), "r"(a[3]), "r"(b[0]), "r"(b[1]));
}
__device__ __forceinline__ void cp16(uint32_t dst, const void* src) {
    asm volatile("cp.async.cg.shared.global [%0], [%1], 16;" :: "r"(dst), "l"(src));
}
__device__ __forceinline__ void stg64_cs(float* p, float2 v) {
    asm volatile("st.global.cs.v2.f32 [%0], {%1,%2};"
                 :: "l"(p), "f"(v.x), "f"(v.y) : "memory");
}
__device__ __forceinline__ uint32_t bits(__nv_bfloat162 v) {
    return *reinterpret_cast<uint32_t*>(&v);
}

// exact value for non-underflow elements (rare): fp32 dot from global
__device__ __noinline__ float precise_val(const float* __restrict__ X,
                                          const float* __restrict__ Y,
                                          int m, int n, float xpy) {
    const float4* xr = reinterpret_cast<const float4*>(X + (size_t)m * KD);
    const float4* yr = reinterpret_cast<const float4*>(Y + (size_t)n * KD);
    float dot = 0.0f;
#pragma unroll
    for (int i = 0; i < KD / 4; i++) {
        float4 a = xr[i], b = yr[i];
        dot = fmaf(a.x, b.x, dot); dot = fmaf(a.y, b.y, dot);
        dot = fmaf(a.z, b.z, dot); dot = fmaf(a.w, b.w, dot);
    }
    return __expf(-fmaxf(fmaf(-2.0f, dot, xpy), 0.0f));
}

__device__ __forceinline__ float filtered_val(const float* X, const float* Y,
                                              int m, int n, float dot_hi, float xpy) {
    float sq_hi = fmaf(-2.0f, dot_hi, xpy);
    if (sq_hi < 89.2f + 0.008f * xpy)
        return precise_val(X, Y, m, n, xpy);
    return 0.0f;
}

// ---------------- prep: norms + bf16 hi (warp per row) ----------------
__global__ void rbf_prep_kernel(const float* __restrict__ x,
                                const float* __restrict__ y) {
    int gw = (blockIdx.x * blockDim.x + threadIdx.x) >> 5;
    int lane = threadIdx.x & 31;
    if (gw >= 2 * NM) return;
    bool isX = gw < NM;
    int row = isX ? gw : gw - NM;
    const float* src = isX ? x : y;
    __nv_bfloat16* hid = isX ? g_xhi : g_yhi;
    float* nrm = isX ? g_x2 : g_y2;

    float4 v = reinterpret_cast<const float4*>(src + (size_t)row * KD)[lane];
    __nv_bfloat162 h01 = __floats2bfloat162_rn(v.x, v.y);
    __nv_bfloat162 h23 = __floats2bfloat162_rn(v.z, v.w);
    *reinterpret_cast<uint2*>(hid + (size_t)row * KD + lane * 4) =
        make_uint2(bits(h01), bits(h23));

    float s = fmaf(v.x, v.x, fmaf(v.y, v.y, fmaf(v.z, v.z, v.w * v.w)));
#pragma unroll
    for (int o = 16; o > 0; o >>= 1) s += __shfl_xor_sync(0xFFFFFFFFu, s, o);
    if (lane == 0) nrm[row] = s;
}

// ---------------- main MMA filter kernel ----------------
// CTA 128x128, 16 warps (4 M x 4 N), warp tile 32x32, full K=128 resident.
// smem 64 KB (2 CTA/SM @ 64 regs): Ahi [0,32K) = 2 k-panels x 16 KB (128 rows
// x 128B, 8 x 16B chunks, chunk ^= row&7); Bhi [32K,64K) same.
__global__ __launch_bounds__(512, 2)
void rbf_mma_kernel(const float* __restrict__ X,
                    const float* __restrict__ Y,
                    float* __restrict__ O) {
    extern __shared__ char sm[];
    __shared__ float x2s[CTA_M];
    __shared__ float y2s[CTA_N];

    const int tid = threadIdx.x;
    const int wid = tid >> 5;
    const int lane = tid & 31;
    const int wm = wid >> 2;       // 0..3 (32 rows each)
    const int wn = wid & 3;        // 0..3 (32 cols each)

    // 8x8 supertile swizzle
    const int bid = blockIdx.x;
    const int band   = bid / (SUPER * GRID_W);
    const int within = bid % (SUPER * GRID_W);
    const int tx = within / SUPER;
    const int ty = band * SUPER + (within % SUPER);
    const int mBase = ty * CTA_M;
    const int nBase = tx * CTA_N;

    const uint32_t sA = smem_u32(sm);
    const uint32_t sB = sA + 32768u;

    // fill: 2048 16B chunks per tensor over 512 threads -> 4 iters
#pragma unroll
    for (int i = 0; i < 4; i++) {
        int idx = tid + i * 512;
        int r = idx >> 4, j = idx & 15;
        uint32_t off = (uint32_t)((j >> 3) * 16384 + r * 128 + (((j & 7) ^ (r & 7)) << 4));
        cp16(sA + off, g_xhi + (size_t)(mBase + r) * KD + j * 8);
        cp16(sB + off, g_yhi + (size_t)(nBase + r) * KD + j * 8);
    }
    asm volatile("cp.async.commit_group;" ::: "memory");

    if (tid < CTA_M) x2s[tid] = g_x2[mBase + tid];
    else if (tid < CTA_M + CTA_N) y2s[tid - CTA_M] = g_y2[nBase + (tid - CTA_M)];

    float acc[2][4][4];
#pragma unroll
    for (int mt = 0; mt < 2; mt++)
#pragma unroll
        for (int nt = 0; nt < 4; nt++)
#pragma unroll
            for (int r = 0; r < 4; r++) acc[mt][nt][r] = 0.0f;

    const int a_row = wm * 32 + (lane & 15);
    const int a_cs  = lane >> 4;
    const int b_row = wn * 32 + (lane & 7) + ((lane >> 4) << 3);
    const int b_cs  = (lane >> 3) & 1;

    asm volatile("cp.async.wait_group 0;" ::: "memory");
    __syncthreads();

    // -------- mainloop: 8 k16-steps, 8 MMA each --------
#pragma unroll
    for (int ks = 0; ks < 8; ks++) {
        const uint32_t pnl = (uint32_t)((ks >> 2) * 16384);
        const int kc = (ks & 3) * 2;
        uint32_t bh[2][4];
#pragma unroll
        for (int pr = 0; pr < 2; pr++) {
            int rr = b_row + pr * 16;
            ldsm_x4(bh[pr], sB + pnl + (uint32_t)(rr * 128)
                          + (uint32_t)(((kc + b_cs) ^ (rr & 7)) << 4));
        }
#pragma unroll
        for (int mt = 0; mt < 2; mt++) {
            int rr = a_row + mt * 16;
            uint32_t ah[4];
            ldsm_x4(ah, sA + pnl + (uint32_t)(rr * 128)
                      + (uint32_t)(((kc + a_cs) ^ (rr & 7)) << 4));
#pragma unroll
            for (int pr = 0; pr < 2; pr++) {
                mma_bf16(acc[mt][2 * pr],     ah, bh[pr]);
                mma_bf16(acc[mt][2 * pr + 1], ah, bh[pr] + 2);
            }
        }
    }

    // -------- epilogue: filtered values, streaming float2 stores --------
    const int g  = lane >> 2;
    const int t4 = lane & 3;
#pragma unroll
    for (int mt = 0; mt < 2; mt++) {
        int mrow = wm * 32 + mt * 16 + g;
        float xa = x2s[mrow];
        float xb = x2s[mrow + 8];
        int m0 = mBase + mrow;
        float* orow0 = O + (size_t)m0 * NM + nBase;
        float* orow1 = orow0 + (size_t)8 * NM;
#pragma unroll
        for (int nt = 0; nt < 4; nt++) {
            int nc = wn * 32 + nt * 8 + t4 * 2;
            float ya = y2s[nc];
            float yb = y2s[nc + 1];
            const float* a4 = acc[mt][nt];
            int n0 = nBase + nc;
            float2 o0, o1;
            o0.x = filtered_val(X, Y, m0,     n0,     a4[0], xa + ya);
            o0.y = filtered_val(X, Y, m0,     n0 + 1, a4[1], xa + yb);
            o1.x = filtered_val(X, Y, m0 + 8, n0,     a4[2], xb + ya);
            o1.y = filtered_val(X, Y, m0 + 8, n0 + 1, a4[3], xb + yb);
            stg64_cs(orow0 + nc, o0);
            stg64_cs(orow1 + nc, o1);
        }
    }
}

// ---------------------------------------------------------------------------
extern "C" void kernel_launch(void* const* d_in, const int* in_sizes, int n_in,
                              void* d_out, int out_size) {
    const float* x = (const float*)d_in[0];
    const float* y = (const float*)d_in[1];
    float* out = (float*)d_out;

    cudaFuncSetAttribute(rbf_mma_kernel,
                         cudaFuncAttributeMaxDynamicSharedMemorySize, 65536);

    rbf_prep_kernel<<<2048, 256>>>(x, y);

    rbf_mma_kernel<<<GRID_W * GRID_W, 512, 65536>>>(x, y, out);
}

// round 16
// speedup vs baseline: 1.0055x; 1.0055x over previous
#include <cuda_runtime.h>
#include <cuda_bf16.h>
#include <cstdint>

// RBF kernel matrix, bf16-hi HMMA filter + rare precise recompute.
//   Bound: |sq_hi - sq| <= 0.008*(||x||^2+||y||^2)  (bf16 rn eps=2^-8, AM-GM, margin)
//   sq_hi >= 89.2 + 0.008*(x2+y2)  =>  sq > 88  =>  expf(-sq) underflows => 0.0f
//   else: exact fp32 recompute (rare).
// R16 = R15 with FIXED interleaved zero-store indexing: one stg.128 per
// (even ks, mt) -> exactly 16 float4/thread = the CTA's 4096-float4 tile.
// x,y: [8192,128] f32. out: [8192,8192] f32.

#define NM 8192
#define KD 128
#define CTA_M 128
#define CTA_N 128
#define GRID_W (NM / CTA_N)
#define SUPER 8

__device__ float g_x2[NM];
__device__ float g_y2[NM];
__device__ __nv_bfloat16 g_xhi[NM * KD];
__device__ __nv_bfloat16 g_yhi[NM * KD];

// ---------------- helpers ----------------
__device__ __forceinline__ uint32_t smem_u32(const void* p) {
    uint32_t a;
    asm("{ .reg .u64 t; cvta.to.shared.u64 t, %1; cvt.u32.u64 %0, t; }"
        : "=r"(a) : "l"(p));
    return a;
}
__device__ __forceinline__ void ldsm_x4(uint32_t* r, uint32_t addr) {
    asm volatile("ldmatrix.sync.aligned.m8n8.x4.shared.b16 {%0,%1,%2,%3}, [%4];"
                 : "=r"(r[0]), "=r"(r[1]), "=r"(r[2]), "=r"(r[3]) : "r"(addr));
}
__device__ __forceinline__ void mma_bf16(float* d, const uint32_t* a, const uint32_t* b) {
    asm volatile(
        "mma.sync.aligned.m16n8k16.row.col.f32.bf16.bf16.f32 "
        "{%0,%1,%2,%3}, {%4,%5,%6,%7}, {%8,%9}, {%0,%1,%2,%3};"
        : "+f"(d[0]), "+f"(d[1]), "+f"(d[2]), "+f"(d[3])
        : "r"(a[0]), "r"(a[1]), "r"(a[2]), "r"(a[3]), "r"(b[0]), "r"(b[1]));
}
__device__ __forceinline__ void cp16(uint32_t dst, const void* src) {
    asm volatile("cp.async.cg.shared.global [%0], [%1], 16;" :: "r"(dst), "l"(src));
}
__device__ __forceinline__ void stg128_zero_cs(float* p) {
    asm volatile("st.global.cs.v4.f32 [%0], {%1,%1,%1,%1};"
                 :: "l"(p), "f"(0.0f) : "memory");
}
__device__ __forceinline__ uint32_t bits(__nv_bfloat162 v) {
    return *reinterpret_cast<uint32_t*>(&v);
}

// exact value for non-underflow elements (rare): fp32 dot from global
__device__ __noinline__ float precise_val(const float* __restrict__ X,
                                          const float* __restrict__ Y,
                                          int m, int n, float xpy) {
    const float4* xr = reinterpret_cast<const float4*>(X + (size_t)m * KD);
    const float4* yr = reinterpret_cast<const float4*>(Y + (size_t)n * KD);
    float dot = 0.0f;
#pragma unroll
    for (int i = 0; i < KD / 4; i++) {
        float4 a = xr[i], b = yr[i];
        dot = fmaf(a.x, b.x, dot); dot = fmaf(a.y, b.y, dot);
        dot = fmaf(a.z, b.z, dot); dot = fmaf(a.w, b.w, dot);
    }
    return __expf(-fmaxf(fmaf(-2.0f, dot, xpy), 0.0f));
}

// rare path: overwrite the pre-stored zero when underflow can't be certified
__device__ __forceinline__ void maybe_store(const float* X, const float* Y,
                                            float* O, int m, int n,
                                            float dot_hi, float xpy) {
    float sq_hi = fmaf(-2.0f, dot_hi, xpy);
    if (sq_hi < 89.2f + 0.008f * xpy)
        O[(size_t)m * NM + n] = precise_val(X, Y, m, n, xpy);
}

// ---------------- prep: norms + bf16 hi (warp per row) ----------------
__global__ void rbf_prep_kernel(const float* __restrict__ x,
                                const float* __restrict__ y) {
    int gw = (blockIdx.x * blockDim.x + threadIdx.x) >> 5;
    int lane = threadIdx.x & 31;
    if (gw >= 2 * NM) return;
    bool isX = gw < NM;
    int row = isX ? gw : gw - NM;
    const float* src = isX ? x : y;
    __nv_bfloat16* hid = isX ? g_xhi : g_yhi;
    float* nrm = isX ? g_x2 : g_y2;

    float4 v = reinterpret_cast<const float4*>(src + (size_t)row * KD)[lane];
    __nv_bfloat162 h01 = __floats2bfloat162_rn(v.x, v.y);
    __nv_bfloat162 h23 = __floats2bfloat162_rn(v.z, v.w);
    *reinterpret_cast<uint2*>(hid + (size_t)row * KD + lane * 4) =
        make_uint2(bits(h01), bits(h23));

    float s = fmaf(v.x, v.x, fmaf(v.y, v.y, fmaf(v.z, v.z, v.w * v.w)));
#pragma unroll
    for (int o = 16; o > 0; o >>= 1) s += __shfl_xor_sync(0xFFFFFFFFu, s, o);
    if (lane == 0) nrm[row] = s;
}

// ---------------- main MMA filter kernel ----------------
// CTA 128x128, 8 warps (2 M x 4 N), warp tile 64x32, full K=128 resident.
// smem 64 KB (2 CTA/SM): Ahi [0,32K) = 2 k-panels x 16 KB (128 rows x 128B,
// 8 x 16B chunks, chunk ^= row&7); Bhi [32K,64K) same.
// Mainloop interleaves coalesced stg.128 zero-stores (16/thread total);
// epilogue does only rare predicated overwrites after __syncthreads.
__global__ __launch_bounds__(256, 2)
void rbf_mma_kernel(const float* __restrict__ X,
                    const float* __restrict__ Y,
                    float* __restrict__ O) {
    extern __shared__ char sm[];
    __shared__ float x2s[CTA_M];
    __shared__ float y2s[CTA_N];

    const int tid = threadIdx.x;
    const int wid = tid >> 5;
    const int lane = tid & 31;
    const int wm = wid >> 2;
    const int wn = wid & 3;

    // 8x8 supertile swizzle
    const int bid = blockIdx.x;
    const int band   = bid / (SUPER * GRID_W);
    const int within = bid % (SUPER * GRID_W);
    const int tx = within / SUPER;
    const int ty = band * SUPER + (within % SUPER);
    const int mBase = ty * CTA_M;
    const int nBase = tx * CTA_N;

    const uint32_t sA = smem_u32(sm);
    const uint32_t sB = sA + 32768u;

#pragma unroll
    for (int i = 0; i < 8; i++) {
        int idx = tid + i * 256;
        int r = idx >> 4, j = idx & 15;
        uint32_t off = (uint32_t)((j >> 3) * 16384 + r * 128 + (((j & 7) ^ (r & 7)) << 4));
        cp16(sA + off, g_xhi + (size_t)(mBase + r) * KD + j * 8);
        cp16(sB + off, g_yhi + (size_t)(nBase + r) * KD + j * 8);
    }
    asm volatile("cp.async.commit_group;" ::: "memory");

    if (tid < CTA_M) x2s[tid] = g_x2[mBase + tid];
    else             y2s[tid - CTA_M] = g_y2[nBase + (tid - CTA_M)];

    float acc[4][4][4];
#pragma unroll
    for (int mt = 0; mt < 4; mt++)
#pragma unroll
        for (int nt = 0; nt < 4; nt++)
#pragma unroll
            for (int r = 0; r < 4; r++) acc[mt][nt][r] = 0.0f;

    const int a_row = wm * 64 + (lane & 15);
    const int a_cs  = lane >> 4;
    const int b_row = wn * 32 + (lane & 7) + ((lane >> 4) << 3);
    const int b_cs  = (lane >> 3) & 1;

    // zero-store mapping: 16 float4/thread across the loop (even ks only)
    float4* const obase = reinterpret_cast<float4*>(O + (size_t)mBase * NM + nBase);
    const int ldo4 = NM / 4;

    asm volatile("cp.async.wait_group 0;" ::: "memory");
    __syncthreads();

    // -------- mainloop: 8 k16-steps, 16 MMA each; zeros on even ks --------
#pragma unroll
    for (int ks = 0; ks < 8; ks++) {
        const uint32_t pnl = (uint32_t)((ks >> 2) * 16384);
        const int kc = (ks & 3) * 2;
        uint32_t bh[2][4];
#pragma unroll
        for (int pr = 0; pr < 2; pr++) {
            int rr = b_row + pr * 16;
            ldsm_x4(bh[pr], sB + pnl + (uint32_t)(rr * 128)
                          + (uint32_t)(((kc + b_cs) ^ (rr & 7)) << 4));
        }
#pragma unroll
        for (int mt = 0; mt < 4; mt++) {
            int rr = a_row + mt * 16;
            uint32_t ah[4];
            ldsm_x4(ah, sA + pnl + (uint32_t)(rr * 128)
                      + (uint32_t)(((kc + a_cs) ^ (rr & 7)) << 4));
#pragma unroll
            for (int pr = 0; pr < 2; pr++) {
                mma_bf16(acc[mt][2 * pr],     ah, bh[pr]);
                mma_bf16(acc[mt][2 * pr + 1], ah, bh[pr] + 2);
            }
            // interleaved zero-store: slot = (ks>>1)*4 + mt in 0..15
            if ((ks & 1) == 0) {
                int idx = tid + (((ks >> 1) * 4 + mt) << 8);   // 0..4095
                int r = idx >> 5, c4 = idx & 31;
                stg128_zero_cs(reinterpret_cast<float*>(obase + (size_t)r * ldo4 + c4));
            }
        }
    }

    __syncthreads();   // all zero-stores ordered before rare overwrites

    // -------- epilogue: rare predicated overwrites only --------
    const int g  = lane >> 2;
    const int t4 = lane & 3;
#pragma unroll
    for (int mt = 0; mt < 4; mt++) {
        int mrow = wm * 64 + mt * 16 + g;
        float xa = x2s[mrow];
        float xb = x2s[mrow + 8];
        int m0 = mBase + mrow;
#pragma unroll
        for (int nt = 0; nt < 4; nt++) {
            int nc = wn * 32 + nt * 8 + t4 * 2;
            float ya = y2s[nc];
            float yb = y2s[nc + 1];
            const float* a4 = acc[mt][nt];
            int n0 = nBase + nc;
            maybe_store(X, Y, O, m0,     n0,     a4[0], xa + ya);
            maybe_store(X, Y, O, m0,     n0 + 1, a4[1], xa + yb);
            maybe_store(X, Y, O, m0 + 8, n0,     a4[2], xb + ya);
            maybe_store(X, Y, O, m0 + 8, n0 + 1, a4[3], xb + yb);
        }
    }
}

// ---------------------------------------------------------------------------
extern "C" void kernel_launch(void* const* d_in, const int* in_sizes, int n_in,
                              void* d_out, int out_size) {
    const float* x = (const float*)d_in[0];
    const float* y = (const float*)d_in[1];
    float* out = (float*)d_out;

    cudaFuncSetAttribute(rbf_mma_kernel,
                         cudaFuncAttributeMaxDynamicSharedMemorySize, 65536);

    rbf_prep_kernel<<<2048, 256>>>(x, y);

    rbf_mma_kernel<<<GRID_W * GRID_W, 256, 65536>>>(x, y, out);
}

// round 17
// speedup vs baseline: 1.1409x; 1.1347x over previous
#include <cuda_runtime.h>
#include <cuda_bf16.h>
#include <cstdint>

// RBF kernel matrix, bf16-hi HMMA filter + rare precise recompute.
//   Certify-zero filter (exact algebra of the proven bound):
//     refine  <=>  sq_hi < 89.2 + 0.008*(x2+y2)
//             <=>  dot_hi > (0.496*x2 - 44.6) + 0.496*y2 = px[m] + qy[n]
//   certified => expf(-sq) underflows fp32 => 0.0f ; else exact recompute.
// R17 = R12 structure verbatim; epilogue uses precomputed px/qy thresholds
// (1 FADD + 1 FSETP per element). Rare path reloads norms from global.
// x,y: [8192,128] f32. out: [8192,8192] f32.

#define NM 8192
#define KD 128
#define CTA_M 128
#define CTA_N 128
#define GRID_W (NM / CTA_N)
#define SUPER 8

__device__ float g_x2[NM];
__device__ float g_y2[NM];
__device__ __nv_bfloat16 g_xhi[NM * KD];
__device__ __nv_bfloat16 g_yhi[NM * KD];

// ---------------- helpers ----------------
__device__ __forceinline__ uint32_t smem_u32(const void* p) {
    uint32_t a;
    asm("{ .reg .u64 t; cvta.to.shared.u64 t, %1; cvt.u32.u64 %0, t; }"
        : "=r"(a) : "l"(p));
    return a;
}
__device__ __forceinline__ void ldsm_x4(uint32_t* r, uint32_t addr) {
    asm volatile("ldmatrix.sync.aligned.m8n8.x4.shared.b16 {%0,%1,%2,%3}, [%4];"
                 : "=r"(r[0]), "=r"(r[1]), "=r"(r[2]), "=r"(r[3]) : "r"(addr));
}
__device__ __forceinline__ void mma_bf16(float* d, const uint32_t* a, const uint32_t* b) {
    asm volatile(
        "mma.sync.aligned.m16n8k16.row.col.f32.bf16.bf16.f32 "
        "{%0,%1,%2,%3}, {%4,%5,%6,%7}, {%8,%9}, {%0,%1,%2,%3};"
        : "+f"(d[0]), "+f"(d[1]), "+f"(d[2]), "+f"(d[3])
        : "r"(a[0]), "r"(a[1]), "r"(a[2]), "r"(a[3]), "r"(b[0]), "r"(b[1]));
}
__device__ __forceinline__ void cp16(uint32_t dst, const void* src) {
    asm volatile("cp.async.cg.shared.global [%0], [%1], 16;" :: "r"(dst), "l"(src));
}
__device__ __forceinline__ void stg64_cs(float* p, float2 v) {
    asm volatile("st.global.cs.v2.f32 [%0], {%1,%2};"
                 :: "l"(p), "f"(v.x), "f"(v.y) : "memory");
}
__device__ __forceinline__ uint32_t bits(__nv_bfloat162 v) {
    return *reinterpret_cast<uint32_t*>(&v);
}

// exact value for non-certified elements (rare): fp32 dot + norms from global
__device__ __noinline__ float precise_val(const float* __restrict__ X,
                                          const float* __restrict__ Y,
                                          int m, int n) {
    const float4* xr = reinterpret_cast<const float4*>(X + (size_t)m * KD);
    const float4* yr = reinterpret_cast<const float4*>(Y + (size_t)n * KD);
    float dot = 0.0f;
#pragma unroll
    for (int i = 0; i < KD / 4; i++) {
        float4 a = xr[i], b = yr[i];
        dot = fmaf(a.x, b.x, dot); dot = fmaf(a.y, b.y, dot);
        dot = fmaf(a.z, b.z, dot); dot = fmaf(a.w, b.w, dot);
    }
    float xpy = g_x2[m] + g_y2[n];
    return __expf(-fmaxf(fmaf(-2.0f, dot, xpy), 0.0f));
}

// common path: certified-zero unless dot_hi exceeds threshold t = px+qy
__device__ __forceinline__ float filtered_val(const float* X, const float* Y,
                                              int m, int n, float dot_hi, float t) {
    if (dot_hi > t) return precise_val(X, Y, m, n);
    return 0.0f;
}

// ---------------- prep: norms + bf16 hi (warp per row) ----------------
__global__ void rbf_prep_kernel(const float* __restrict__ x,
                                const float* __restrict__ y) {
    int gw = (blockIdx.x * blockDim.x + threadIdx.x) >> 5;
    int lane = threadIdx.x & 31;
    if (gw >= 2 * NM) return;
    bool isX = gw < NM;
    int row = isX ? gw : gw - NM;
    const float* src = isX ? x : y;
    __nv_bfloat16* hid = isX ? g_xhi : g_yhi;
    float* nrm = isX ? g_x2 : g_y2;

    float4 v = reinterpret_cast<const float4*>(src + (size_t)row * KD)[lane];
    __nv_bfloat162 h01 = __floats2bfloat162_rn(v.x, v.y);
    __nv_bfloat162 h23 = __floats2bfloat162_rn(v.z, v.w);
    *reinterpret_cast<uint2*>(hid + (size_t)row * KD + lane * 4) =
        make_uint2(bits(h01), bits(h23));

    float s = fmaf(v.x, v.x, fmaf(v.y, v.y, fmaf(v.z, v.z, v.w * v.w)));
#pragma unroll
    for (int o = 16; o > 0; o >>= 1) s += __shfl_xor_sync(0xFFFFFFFFu, s, o);
    if (lane == 0) nrm[row] = s;
}

// ---------------- main MMA filter kernel (R12 + threshold epilogue) --------
// CTA 128x128, 8 warps (2 M x 4 N), warp tile 64x32, full K=128 resident.
// smem 64 KB (2 CTA/SM): Ahi [0,32K) = 2 k-panels x 16 KB (128 rows x 128B,
// 8 x 16B chunks, chunk ^= row&7); Bhi [32K,64K) same.
__global__ __launch_bounds__(256, 2)
void rbf_mma_kernel(const float* __restrict__ X,
                    const float* __restrict__ Y,
                    float* __restrict__ O) {
    extern __shared__ char sm[];
    __shared__ float pxs[CTA_M];   // 0.496*x2 - 44.6
    __shared__ float qys[CTA_N];   // 0.496*y2

    const int tid = threadIdx.x;
    const int wid = tid >> 5;
    const int lane = tid & 31;
    const int wm = wid >> 2;
    const int wn = wid & 3;

    // 8x8 supertile swizzle
    const int bid = blockIdx.x;
    const int band   = bid / (SUPER * GRID_W);
    const int within = bid % (SUPER * GRID_W);
    const int tx = within / SUPER;
    const int ty = band * SUPER + (within % SUPER);
    const int mBase = ty * CTA_M;
    const int nBase = tx * CTA_N;

    const uint32_t sA = smem_u32(sm);
    const uint32_t sB = sA + 32768u;

#pragma unroll
    for (int i = 0; i < 8; i++) {
        int idx = tid + i * 256;
        int r = idx >> 4, j = idx & 15;
        uint32_t off = (uint32_t)((j >> 3) * 16384 + r * 128 + (((j & 7) ^ (r & 7)) << 4));
        cp16(sA + off, g_xhi + (size_t)(mBase + r) * KD + j * 8);
        cp16(sB + off, g_yhi + (size_t)(nBase + r) * KD + j * 8);
    }
    asm volatile("cp.async.commit_group;" ::: "memory");

    if (tid < CTA_M) pxs[tid] = fmaf(0.496f, g_x2[mBase + tid], -44.6f);
    else             qys[tid - CTA_M] = 0.496f * g_y2[nBase + (tid - CTA_M)];

    float acc[4][4][4];
#pragma unroll
    for (int mt = 0; mt < 4; mt++)
#pragma unroll
        for (int nt = 0; nt < 4; nt++)
#pragma unroll
            for (int r = 0; r < 4; r++) acc[mt][nt][r] = 0.0f;

    const int a_row = wm * 64 + (lane & 15);
    const int a_cs  = lane >> 4;
    const int b_row = wn * 32 + (lane & 7) + ((lane >> 4) << 3);
    const int b_cs  = (lane >> 3) & 1;

    asm volatile("cp.async.wait_group 0;" ::: "memory");
    __syncthreads();

    // -------- mainloop: 8 k16-steps, 16 MMA each --------
#pragma unroll
    for (int ks = 0; ks < 8; ks++) {
        const uint32_t pnl = (uint32_t)((ks >> 2) * 16384);
        const int kc = (ks & 3) * 2;
        uint32_t bh[2][4];
#pragma unroll
        for (int pr = 0; pr < 2; pr++) {
            int rr = b_row + pr * 16;
            ldsm_x4(bh[pr], sB + pnl + (uint32_t)(rr * 128)
                          + (uint32_t)(((kc + b_cs) ^ (rr & 7)) << 4));
        }
#pragma unroll
        for (int mt = 0; mt < 4; mt++) {
            int rr = a_row + mt * 16;
            uint32_t ah[4];
            ldsm_x4(ah, sA + pnl + (uint32_t)(rr * 128)
                      + (uint32_t)(((kc + a_cs) ^ (rr & 7)) << 4));
#pragma unroll
            for (int pr = 0; pr < 2; pr++) {
                mma_bf16(acc[mt][2 * pr],     ah, bh[pr]);
                mma_bf16(acc[mt][2 * pr + 1], ah, bh[pr] + 2);
            }
        }
    }

    // -------- epilogue: threshold filter, streaming float2 stores --------
    const int g  = lane >> 2;
    const int t4 = lane & 3;
#pragma unroll
    for (int mt = 0; mt < 4; mt++) {
        int mrow = wm * 64 + mt * 16 + g;
        float pxa = pxs[mrow];
        float pxb = pxs[mrow + 8];
        int m0 = mBase + mrow;
        float* orow0 = O + (size_t)m0 * NM + nBase;
        float* orow1 = orow0 + (size_t)8 * NM;
#pragma unroll
        for (int nt = 0; nt < 4; nt++) {
            int nc = wn * 32 + nt * 8 + t4 * 2;
            float qa = qys[nc];
            float qb = qys[nc + 1];
            const float* a4 = acc[mt][nt];
            int n0 = nBase + nc;
            float2 o0, o1;
            o0.x = filtered_val(X, Y, m0,     n0,     a4[0], pxa + qa);
            o0.y = filtered_val(X, Y, m0,     n0 + 1, a4[1], pxa + qb);
            o1.x = filtered_val(X, Y, m0 + 8, n0,     a4[2], pxb + qa);
            o1.y = filtered_val(X, Y, m0 + 8, n0 + 1, a4[3], pxb + qb);
            stg64_cs(orow0 + nc, o0);
            stg64_cs(orow1 + nc, o1);
        }
    }
}

// ---------------------------------------------------------------------------
extern "C" void kernel_launch(void* const* d_in, const int* in_sizes, int n_in,
                              void* d_out, int out_size) {
    const float* x = (const float*)d_in[0];
    const float* y = (const float*)d_in[1];
    float* out = (float*)d_out;

    cudaFuncSetAttribute(rbf_mma_kernel,
                         cudaFuncAttributeMaxDynamicSharedMemorySize, 65536);

    rbf_prep_kernel<<<2048, 256>>>(x, y);

    rbf_mma_kernel<<<GRID_W * GRID_W, 256, 65536>>>(x, y, out);
}